// round 16
// baseline (speedup 1.0000x reference)
#include <cuda_runtime.h>

#define SPB 37           // samples per chunk: 18 warps x 2 + warp18 x 1
#define WARPS 19
#define THREADS (WARPS*32)   // 608
#define GRID 148             // persistent: one block per SM, warps loop over chunks

// ---- weight offsets in shared (floats) ----
enum {
  EW1=0, EB1=192, EW2P=256, EB2P=4352, EW3P=4416, EB3=4672,
  G1WL=4676, G1BL=4868, G1WR=4932, G1BR=5124, G1WE=5188, G1ATT=5252 /*0.4*att*/, G1BIAS=5316,
  G2WLT=5380, G2BL4=5572, G2WRT=5576, G2BR4=5768,
  G2WE4=5772, G2ATT4=5776, G2BIAS4=5780,
  SKW=5784, SKB=5796,
  DW1=5800, DB1=5992, DW2P=6056, DB2P=10152, DW3P=10216, DB3=10472,
  G1A06=10476 /*0.6*att*/, WQ6=10540 /*0.6*sum(att*we)*/,
  WTOT=10544
};
// ---- per-sample scratch (floats); heavy lifetime overlays ----
// SLJ (8 fl) overlays SVIS head (dead after Gabriel; SCOMB written later).
enum {
  SA=0, SLATP=512, SXL=0, SXR=544, SXL2=0, SXR2=32,
  SEM=1084, SX=1084, SALPHA=1148, SLAT=1212, SVIS=1244, SCOMB=1244, SLJ=1244,
  SPER=1276
};

#define SMEM_FLOATS (WTOT + SPB*SPER)
#define SMEM_BYTES  (SMEM_FLOATS*4)   // 231,024 B -> 1 block/SM

struct KParams {
  const float* x;
  const float* w[28];
  int B;
  int nChunks;
};

extern __shared__ float smem[];

__device__ __forceinline__ void cpy(float* dst, const float* src, int n, int tid) {
  for (int i = tid; i < n; i += THREADS) dst[i] = src[i];
}

__device__ __forceinline__ float lrelu(float h) { return fmaxf(h, 0.2f*h); }

__device__ __forceinline__ float frcp(float x) {
  float r; asm("rcp.approx.f32 %0, %1;" : "=f"(r) : "f"(x)); return r;
}
__device__ __forceinline__ float fsqrt_ap(float x) {
  float r; asm("sqrt.approx.f32 %0, %1;" : "=f"(r) : "f"(x)); return r;
}

__device__ __forceinline__ unsigned sm_u32(const void* p) {
  unsigned a;
  asm("{ .reg .u64 t; cvta.to.shared.u64 t, %1; cvt.u32.u64 %0, t; }"
      : "=r"(a) : "l"(p));
  return a;
}

// Dual-sample 8x64 @ 64x64 + relu + fused (64->3) projection; f32x2 with
// NODE-PAIR packed accumulators. Warp18 (sc1==sc0) duplicates; idempotent.
__device__ __forceinline__ void mlp64_dual(
    const float* __restrict__ in0, const float* __restrict__ in1,
    float* sc0, float* sc1,
    const float* __restrict__ Wp, const float* __restrict__ bp,
    const float* __restrict__ W3p, int t)
{
  const int u = t & 1, cg = t >> 1;
  const unsigned abase = sm_u32(u ? in1 : in0);
  const unsigned wbase = sm_u32(Wp) + cg*16u;

  float4 b4 = *(const float4*)&bp[cg*4];
  unsigned long long D0[4], D1[4], D2[4], D3[4];
  {
    unsigned long long bd0, bd1, bd2, bd3;
    asm("mov.b64 %0, {%1,%1};" : "=l"(bd0) : "f"(b4.x));
    asm("mov.b64 %0, {%1,%1};" : "=l"(bd1) : "f"(b4.y));
    asm("mov.b64 %0, {%1,%1};" : "=l"(bd2) : "f"(b4.z));
    asm("mov.b64 %0, {%1,%1};" : "=l"(bd3) : "f"(b4.w));
#pragma unroll
    for (int p = 0; p < 4; p++) { D0[p]=bd0; D1[p]=bd1; D2[p]=bd2; D3[p]=bd3; }
  }

#pragma unroll 4
  for (int k = 0; k < 64; k++) {
    unsigned aa = abase + (unsigned)(k*32);
    unsigned wa = wbase + (unsigned)(k*256);
    unsigned long long ar0, ar1, ar2, ar3, w01, w23;
    asm("ld.shared.v2.u64 {%0,%1}, [%2];" : "=l"(ar0), "=l"(ar1) : "r"(aa));
    asm("ld.shared.v2.u64 {%0,%1}, [%2];" : "=l"(ar2), "=l"(ar3) : "r"(aa+16u));
    asm("ld.shared.v2.u64 {%0,%1}, [%2];" : "=l"(w01), "=l"(w23) : "r"(wa));
    float w0, w1, w2, w3;
    asm("mov.b64 {%0,%1}, %2;" : "=f"(w0), "=f"(w1) : "l"(w01));
    asm("mov.b64 {%0,%1}, %2;" : "=f"(w2), "=f"(w3) : "l"(w23));
    unsigned long long wd0, wd1, wd2, wd3;
    asm("mov.b64 %0, {%1,%1};" : "=l"(wd0) : "f"(w0));
    asm("mov.b64 %0, {%1,%1};" : "=l"(wd1) : "f"(w1));
    asm("mov.b64 %0, {%1,%1};" : "=l"(wd2) : "f"(w2));
    asm("mov.b64 %0, {%1,%1};" : "=l"(wd3) : "f"(w3));
    asm("fma.rn.f32x2 %0, %1, %2, %0;" : "+l"(D0[0]) : "l"(wd0), "l"(ar0));
    asm("fma.rn.f32x2 %0, %1, %2, %0;" : "+l"(D0[1]) : "l"(wd0), "l"(ar1));
    asm("fma.rn.f32x2 %0, %1, %2, %0;" : "+l"(D0[2]) : "l"(wd0), "l"(ar2));
    asm("fma.rn.f32x2 %0, %1, %2, %0;" : "+l"(D0[3]) : "l"(wd0), "l"(ar3));
    asm("fma.rn.f32x2 %0, %1, %2, %0;" : "+l"(D1[0]) : "l"(wd1), "l"(ar0));
    asm("fma.rn.f32x2 %0, %1, %2, %0;" : "+l"(D1[1]) : "l"(wd1), "l"(ar1));
    asm("fma.rn.f32x2 %0, %1, %2, %0;" : "+l"(D1[2]) : "l"(wd1), "l"(ar2));
    asm("fma.rn.f32x2 %0, %1, %2, %0;" : "+l"(D1[3]) : "l"(wd1), "l"(ar3));
    asm("fma.rn.f32x2 %0, %1, %2, %0;" : "+l"(D2[0]) : "l"(wd2), "l"(ar0));
    asm("fma.rn.f32x2 %0, %1, %2, %0;" : "+l"(D2[1]) : "l"(wd2), "l"(ar1));
    asm("fma.rn.f32x2 %0, %1, %2, %0;" : "+l"(D2[2]) : "l"(wd2), "l"(ar2));
    asm("fma.rn.f32x2 %0, %1, %2, %0;" : "+l"(D2[3]) : "l"(wd2), "l"(ar3));
    asm("fma.rn.f32x2 %0, %1, %2, %0;" : "+l"(D3[0]) : "l"(wd3), "l"(ar0));
    asm("fma.rn.f32x2 %0, %1, %2, %0;" : "+l"(D3[1]) : "l"(wd3), "l"(ar1));
    asm("fma.rn.f32x2 %0, %1, %2, %0;" : "+l"(D3[2]) : "l"(wd3), "l"(ar2));
    asm("fma.rn.f32x2 %0, %1, %2, %0;" : "+l"(D3[3]) : "l"(wd3), "l"(ar3));
  }

  float A0[8], A1[8], A2[8], A3[8];
#pragma unroll
  for (int p = 0; p < 4; p++) {
    asm("mov.b64 {%0,%1}, %2;" : "=f"(A0[2*p]), "=f"(A0[2*p+1]) : "l"(D0[p]));
    asm("mov.b64 {%0,%1}, %2;" : "=f"(A1[2*p]), "=f"(A1[2*p+1]) : "l"(D1[p]));
    asm("mov.b64 {%0,%1}, %2;" : "=f"(A2[2*p]), "=f"(A2[2*p+1]) : "l"(D2[p]));
    asm("mov.b64 {%0,%1}, %2;" : "=f"(A3[2*p]), "=f"(A3[2*p+1]) : "l"(D3[p]));
  }
#pragma unroll
  for (int n = 0; n < 8; n++) {
    A0[n] = fmaxf(A0[n], 0.f); A1[n] = fmaxf(A1[n], 0.f);
    A2[n] = fmaxf(A2[n], 0.f); A3[n] = fmaxf(A3[n], 0.f);
  }

  const int p0i = cg*4;
  float4 E0 = *(const float4*)&W3p[(p0i+0)*4];
  float4 E1 = *(const float4*)&W3p[(p0i+1)*4];
  float4 E2 = *(const float4*)&W3p[(p0i+2)*4];
  float4 E3 = *(const float4*)&W3p[(p0i+3)*4];

  float p0[8], p1[8], p2[8];
#pragma unroll
  for (int n = 0; n < 8; n++) {
    p0[n] = fmaf(A0[n],E0.x, fmaf(A1[n],E1.x, fmaf(A2[n],E2.x, A3[n]*E3.x)));
    p1[n] = fmaf(A0[n],E0.y, fmaf(A1[n],E1.y, fmaf(A2[n],E2.y, A3[n]*E3.y)));
    p2[n] = fmaf(A0[n],E0.z, fmaf(A1[n],E1.z, fmaf(A2[n],E2.z, A3[n]*E3.z)));
  }

#pragma unroll
  for (int m = 2; m <= 16; m <<= 1) {
#pragma unroll
    for (int n = 0; n < 8; n++) {
      p0[n] += __shfl_xor_sync(0xffffffffu, p0[n], m);
      p1[n] += __shfl_xor_sync(0xffffffffu, p1[n], m);
      p2[n] += __shfl_xor_sync(0xffffffffu, p2[n], m);
    }
  }
  if (cg == 0) {
    float* d = (u ? sc1 : sc0) + SLATP;
#pragma unroll
    for (int n = 0; n < 8; n++) {
      d[n*3 + 0] = p0[n]; d[n*3 + 1] = p1[n]; d[n*3 + 2] = p2[n];
    }
  }
  __syncwarp();
}

__global__ __launch_bounds__(THREADS, 1)
void gae15_kernel(KParams kp, float* __restrict__ out)
{
  float* ws = smem;
  const int tid = threadIdx.x;
  const int g = tid >> 5;
  const int t = tid & 31;

  // ================= stage weights (ONCE per SM) =================
  cpy(ws+EW1, kp.w[0], 192, tid); cpy(ws+EB1, kp.w[1], 64, tid);
  cpy(ws+EW2P, kp.w[2], 4096, tid);
  cpy(ws+EB2P, kp.w[3], 64, tid);
  { const float* w4 = kp.w[4];
    for (int i = tid; i < 256; i += THREADS) {
      int c = i >> 2, l = i & 3;
      ws[EW3P + i] = (l < 3) ? w4[c*3 + l] : 0.f;
    } }
  if (tid < 4) ws[EB3+tid] = (tid < 3) ? kp.w[5][tid] : 0.f;
  cpy(ws+G1WL, kp.w[6], 192, tid);  cpy(ws+G1BL, kp.w[7], 64, tid);
  cpy(ws+G1WR, kp.w[8], 192, tid);  cpy(ws+G1BR, kp.w[9], 64, tid);
  cpy(ws+G1WE, kp.w[10], 64, tid);
  { const float* at = kp.w[11];
    for (int i = tid; i < 64; i += THREADS) {
      ws[G1ATT + i]  = 0.4f*at[i];
      ws[G1A06 + i]  = 0.6f*at[i];
    } }
  cpy(ws+G1BIAS, kp.w[12], 64, tid);
  { const float* wl = kp.w[13]; const float* wr = kp.w[15];
    for (int i = tid; i < 192; i += THREADS) {
      int k = i / 3, l = i - k*3;
      ws[G2WLT + l*64 + k] = wl[i];
      ws[G2WRT + l*64 + k] = wr[i];
    } }
  if (tid < 4) {
    ws[G2BL4 + tid]   = (tid < 3) ? kp.w[14][tid] : 0.f;
    ws[G2BR4 + tid]   = (tid < 3) ? kp.w[16][tid] : 0.f;
    ws[G2WE4 + tid]   = (tid < 3) ? kp.w[17][tid] : 0.f;
    ws[G2ATT4 + tid]  = (tid < 3) ? kp.w[18][tid] : 0.f;
    ws[G2BIAS4 + tid] = (tid < 3) ? kp.w[19][tid] : 0.f;
  }
  if (tid < 12) ws[SKW+tid] = (tid < 9) ? kp.w[20][tid] : 0.f;
  if (tid < 4)  ws[SKB+tid] = (tid < 3) ? kp.w[21][tid] : 0.f;
  cpy(ws+DW1, kp.w[22], 192, tid); cpy(ws+DB1, kp.w[23], 64, tid);
  cpy(ws+DW2P, kp.w[24], 4096, tid);
  cpy(ws+DB2P, kp.w[25], 64, tid);
  { const float* w26 = kp.w[26];
    for (int i = tid; i < 256; i += THREADS) {
      int c = i >> 2, l = i & 3;
      ws[DW3P + i] = (l < 3) ? w26[c*3 + l] : 0.f;
    } }
  if (tid < 4) ws[DB3+tid] = (tid < 3) ? kp.w[27][tid] : 0.f;

  // WQ6 = 0.6*sum(att*we) computed from global by warp 0 (before syncthreads)
  if (g == 0) {
    const float* wep = kp.w[10]; const float* atp = kp.w[11];
    float v = fmaf(wep[t], atp[t], wep[t+32]*atp[t+32]);
#pragma unroll
    for (int m = 16; m; m >>= 1) v += __shfl_xor_sync(0xffffffffu, v, m);
    if (t == 0) ws[WQ6] = 0.6f*v;
  }

  const int Btot = kp.B;
  const bool ok1 = (g < WARPS-1);
  const int slot1 = ok1 ? (2*g + 1) : 2*g;     // warp18: sc1 aliases sc0
  float* sc0 = smem + WTOT + (2*g)*SPER;
  float* sc1 = smem + WTOT + slot1*SPER;
  const int n3 = t / 3, l3 = t - n3*3;

  __syncthreads();   // weights visible; warps independent hereafter

  // ================= persistent chunk loop (warp-local) =================
  for (int chunk = blockIdx.x; chunk < kp.nChunks; chunk += GRID) {

  const int s0 = chunk*SPB + 2*g;
  const int s1 = s0 + 1;
  const bool v0 = (s0 < Btot);
  const bool v1 = ok1 && (s1 < Btot);

  if (t < 8) {
    sc0[SX + t] = kp.x[(v0 ? s0 : Btot-1)*8 + t];
    if (ok1) sc1[SX + t] = kp.x[(v1 ? s1 : Btot-1)*8 + t];
  }
  __syncwarp();

  // ================= encoder L1 (3->64), layout [c][n] stride 8 =================
  {
    float wn1 = ws[EW1+64+t],    wx1 = ws[EW1+128+t],    bb1 = ws[EB1+t];
    float wn2 = ws[EW1+64+t+32], wx2 = ws[EW1+128+t+32], bb2 = ws[EB1+t+32];
#pragma unroll
    for (int u = 0; u < 2; u++) {
      float* sc = u ? sc1 : sc0;
      float va[8], vb[8];
#pragma unroll
      for (int n = 0; n < 8; n++) {
        float xn = sc[SX + n];
        va[n] = fmaxf(fmaf(xn, wx1, fmaf((float)n, wn1, bb1)), 0.f);
        vb[n] = fmaxf(fmaf(xn, wx2, fmaf((float)n, wn2, bb2)), 0.f);
      }
      *(float4*)&sc[SA + t*8]          = make_float4(va[0],va[1],va[2],va[3]);
      *(float4*)&sc[SA + t*8 + 4]      = make_float4(va[4],va[5],va[6],va[7]);
      *(float4*)&sc[SA + (t+32)*8]     = make_float4(vb[0],vb[1],vb[2],vb[3]);
      *(float4*)&sc[SA + (t+32)*8 + 4] = make_float4(vb[4],vb[5],vb[6],vb[7]);
    }
  }
  __syncwarp();

  // ================= encoder L2+L3 (dual-sample) =================
  mlp64_dual(sc0 + SA, sc1 + SA, sc0, sc1, ws + EW2P, ws + EB2P, ws + EW3P, t);

#pragma unroll
  for (int u = 0; u < 2; u++) {
    float* sc = u ? sc1 : sc0;
    if (t < 24) sc[SLAT + n3*4 + l3] = sc[SLATP + t] + ws[EB3 + l3];
  }
  __syncwarp();

  // ================= normalize -> vis + xp/vis outputs (IEEE: feeds adj) ======
#pragma unroll
  for (int u = 0; u < 2; u++) {
    float* sc = u ? sc1 : sc0;
    const bool vU = u ? v1 : v0;
    const int sU = u ? s1 : s0;
    int ln_l = t >> 3, ln_n = t & 7;
    float v = sc[SLAT + ln_n*4 + ((ln_l < 3) ? ln_l : 0)];
    float sm = v;
    sm += __shfl_xor_sync(0xffffffffu, sm, 1);
    sm += __shfl_xor_sync(0xffffffffu, sm, 2);
    sm += __shfl_xor_sync(0xffffffffu, sm, 4);
    float c = v - sm*0.125f;
    float vv = c*c;
    vv += __shfl_xor_sync(0xffffffffu, vv, 1);
    vv += __shfl_xor_sync(0xffffffffu, vv, 2);
    vv += __shfl_xor_sync(0xffffffffu, vv, 4);
    float inv = 1.f / (sqrtf(vv * (1.f/7.f)) + 1e-8f);
    float visv = c*inv;
    if (t < 24) {
      sc[SVIS + ln_n*4 + ln_l] = visv;
      if (vU) {
        out[2*Btot*24 + sU*24 + ln_n*3 + ln_l] = visv;
        float xpv = (l3 == 0) ? 0.f : ((l3 == 1) ? (float)n3 : sc[SX + n3]);
        out[sU*24 + t] = xpv;
      }
    }
  }
  __syncwarp();

  // ================= Gabriel graph (2 pairs per lane per sample) =================
#pragma unroll
  for (int u = 0; u < 2; u++) {
    float* sc = u ? sc1 : sc0;
    const bool vU = u ? v1 : v0;
    const int sU = u ? s1 : s0;
    float4 Pv[8];
#pragma unroll
    for (int n = 0; n < 8; n++) Pv[n] = *(const float4*)&sc[SVIS + n*4];
    int i0 = t >> 3, j0 = t & 7;
    int i1 = (t + 32) >> 3;
    float4 pi0 = Pv[i0], pj0 = Pv[j0], pi1 = Pv[i1];
    float a0, d0, a1, d1;
    {
      float mx=(pi0.x+pj0.x)*0.5f, my=(pi0.y+pj0.y)*0.5f, mz=(pi0.z+pj0.z)*0.5f;
      float rx=pi0.x-mx, ry=pi0.y-my, rz=pi0.z-mz;
      float r2 = rx*rx+ry*ry+rz*rz;
      bool viol = false;
#pragma unroll
      for (int k = 0; k < 8; k++) {
        float ex=Pv[k].x-mx, ey=Pv[k].y-my, ez=Pv[k].z-mz;
        float d2 = ex*ex+ey*ey+ez*ez;
        viol |= (k != i0) && (k != j0) && (d2 < r2);
      }
      a0 = (!viol && (i0 != j0)) ? 1.f : 0.f;
      float dx=pi0.x-pj0.x, dy=pi0.y-pj0.y, dz=pi0.z-pj0.z;
      d0 = fsqrt_ap(dx*dx+dy*dy+dz*dz + 1e-30f);
    }
    {
      float mx=(pi1.x+pj0.x)*0.5f, my=(pi1.y+pj0.y)*0.5f, mz=(pi1.z+pj0.z)*0.5f;
      float rx=pi1.x-mx, ry=pi1.y-my, rz=pi1.z-mz;
      float r2 = rx*rx+ry*ry+rz*rz;
      bool viol = false;
#pragma unroll
      for (int k = 0; k < 8; k++) {
        float ex=Pv[k].x-mx, ey=Pv[k].y-my, ez=Pv[k].z-mz;
        float d2 = ex*ex+ey*ey+ez*ez;
        viol |= (k != i1) && (k != j0) && (d2 < r2);
      }
      a1 = (!viol && (i1 != j0)) ? 1.f : 0.f;
      float dx=pi1.x-pj0.x, dy=pi1.y-pj0.y, dz=pi1.z-pj0.z;
      d1 = fsqrt_ap(dx*dx+dy*dy+dz*dz + 1e-30f);
    }
    float as = a0 + a1, ds = a0*d0 + a1*d1;
#pragma unroll
    for (int m = 16; m; m >>= 1) {
      as += __shfl_xor_sync(0xffffffffu, as, m);
      ds += __shfl_xor_sync(0xffffffffu, ds, m);
    }
    float ma = ds * frcp(fmaxf(as, 1.f));
    sc[SEM + t]      = (i0 == j0) ? ma : (a0 > 0.f ? d0 : -1.f);
    sc[SEM + t + 32] = (i1 == j0) ? ma : (a1 > 0.f ? d1 : -1.f);
    if (vU) {
      out[3*Btot*24 + sU*64 + t]      = a0;
      out[3*Btot*24 + sU*64 + t + 32] = a1;
    }
  }
  __syncwarp();

  // ========= GAT1 linear (3->64 xl, xr), channel-pair lanes, float2 stores =====
  {
    float2 wl0 = *(const float2*)&ws[G1WL + 2*t];
    float2 wl1 = *(const float2*)&ws[G1WL + 64 + 2*t];
    float2 wl2 = *(const float2*)&ws[G1WL + 128 + 2*t];
    float2 bl  = *(const float2*)&ws[G1BL + 2*t];
    float2 wr0 = *(const float2*)&ws[G1WR + 2*t];
    float2 wr1 = *(const float2*)&ws[G1WR + 64 + 2*t];
    float2 wr2 = *(const float2*)&ws[G1WR + 128 + 2*t];
    float2 br  = *(const float2*)&ws[G1BR + 2*t];
#pragma unroll
    for (int u = 0; u < 2; u++) {
      float* sc = u ? sc1 : sc0;
#pragma unroll
      for (int n = 0; n < 8; n++) {
        float4 la = *(const float4*)&sc[SLAT + n*4];
        float2 xl, xr;
        xl.x = fmaf(la.x, wl0.x, fmaf(la.y, wl1.x, fmaf(la.z, wl2.x, bl.x)));
        xl.y = fmaf(la.x, wl0.y, fmaf(la.y, wl1.y, fmaf(la.z, wl2.y, bl.y)));
        xr.x = fmaf(la.x, wr0.x, fmaf(la.y, wr1.x, fmaf(la.z, wr2.x, br.x)));
        xr.y = fmaf(la.x, wr0.y, fmaf(la.y, wr1.y, fmaf(la.z, wr2.y, br.y)));
        *(float2*)&sc[SXL + n*68 + 2*t] = xl;
        *(float2*)&sc[SXR + n*68 + 2*t] = xr;
      }
    }
  }
  __syncwarp();

  // ===== L06_j = sum_c 0.6*att_c * xl_j,c  (16 lanes: u=t>>3, j=t&7) ==========
  if (t < 16) {
    float* sc = (t >> 3) ? sc1 : sc0;
    int j = t & 7;
    const float* xlp = sc + SXL + j*68;
    float acc = 0.f;
#pragma unroll
    for (int c = 0; c < 64; c += 4) {
      float4 xv = *(const float4*)&xlp[c];
      float4 a6 = *(const float4*)&ws[G1A06 + c];
      acc = fmaf(xv.x, a6.x, fmaf(xv.y, a6.y, fmaf(xv.z, a6.z, fmaf(xv.w, a6.w, acc))));
    }
    sc[SLJ + j] = acc;
  }
  __syncwarp();

  // ===== GAT1 edge scores (row-constant dropped, |h| modifier) + softmax ======
#pragma unroll
  for (int u = 0; u < 2; u++) {
    float* sc = u ? sc1 : sc0;
    const int i = t >> 2;
    const int jj = (t & 3) * 2;
    const float* xr = sc + SXR + i*68;
    const float* xa = sc + SXL + jj*68;
    float2 em = *(const float2*)&sc[SEM + 2*t];
    float mk0 = (em.x >= 0.f) ? 1.f : 0.f;
    float mk1 = (em.y >= 0.f) ? 1.f : 0.f;
    float acc0 = 0.f, acc1 = 0.f;
#pragma unroll 4
    for (int c = 0; c < 64; c += 4) {
      float4 r  = *(const float4*)&xr[c];
      float4 l0 = *(const float4*)&xa[c];
      float4 l1 = *(const float4*)&xa[c + 68];
      float4 we = *(const float4*)&ws[G1WE + c];
      float4 a4 = *(const float4*)&ws[G1ATT + c];   // 0.4*att
      float h;
      h = fmaf(em.x, we.x, r.x) + l0.x; acc0 = fmaf(fabsf(h), a4.x, acc0);
      h = fmaf(em.y, we.x, r.x) + l1.x; acc1 = fmaf(fabsf(h), a4.x, acc1);
      h = fmaf(em.x, we.y, r.y) + l0.y; acc0 = fmaf(fabsf(h), a4.y, acc0);
      h = fmaf(em.y, we.y, r.y) + l1.y; acc1 = fmaf(fabsf(h), a4.y, acc1);
      h = fmaf(em.x, we.z, r.z) + l0.z; acc0 = fmaf(fabsf(h), a4.z, acc0);
      h = fmaf(em.y, we.z, r.z) + l1.z; acc1 = fmaf(fabsf(h), a4.z, acc1);
      h = fmaf(em.x, we.w, r.w) + l0.w; acc0 = fmaf(fabsf(h), a4.w, acc0);
      h = fmaf(em.y, we.w, r.w) + l1.w; acc1 = fmaf(fabsf(h), a4.w, acc1);
    }
    float2 lj = *(const float2*)&sc[SLJ + jj];
    float W6 = ws[WQ6];
    float e0 = (mk0 != 0.f) ? (fmaf(em.x, W6, lj.x) + acc0) : -1e30f;
    float e1 = (mk1 != 0.f) ? (fmaf(em.y, W6, lj.y) + acc1) : -1e30f;
    float m = fmaxf(e0, e1);
    m = fmaxf(m, __shfl_xor_sync(0xffffffffu, m, 1));
    m = fmaxf(m, __shfl_xor_sync(0xffffffffu, m, 2));
    float x0 = __expf(e0 - m), x1 = __expf(e1 - m);
    float sden = x0 + x1;
    sden += __shfl_xor_sync(0xffffffffu, sden, 1);
    sden += __shfl_xor_sync(0xffffffffu, sden, 2);
    float inv = frcp(sden);
    *(float2*)&sc[SALPHA + 2*t] = make_float2(x0*inv*mk0, x1*inv*mk1);
  }
  __syncwarp();

  // ======== GAT1 aggregation -> h1 (into SXR), channel-pair float2 =============
#pragma unroll
  for (int u = 0; u < 2; u++) {
    float* sc = u ? sc1 : sc0;
    float2 acc[8];
    float2 b2 = *(const float2*)&ws[G1BIAS + 2*t];
#pragma unroll
    for (int i = 0; i < 8; i++) acc[i] = b2;
#pragma unroll
    for (int j = 0; j < 8; j += 2) {
      float2 xa = *(const float2*)&sc[SXL + j*68 + 2*t];
      float2 xb = *(const float2*)&sc[SXL + (j+1)*68 + 2*t];
#pragma unroll
      for (int i = 0; i < 8; i++) {
        float2 al = *(const float2*)&sc[SALPHA + i*8 + j];
        acc[i].x = fmaf(al.x, xa.x, fmaf(al.y, xb.x, acc[i].x));
        acc[i].y = fmaf(al.x, xa.y, fmaf(al.y, xb.y, acc[i].y));
      }
    }
    __syncwarp();
#pragma unroll
    for (int i = 0; i < 8; i++) {
      float2 h;
      h.x = fmaxf(acc[i].x, 0.f);
      h.y = fmaxf(acc[i].y, 0.f);
      *(float2*)&sc[SXR + i*68 + 2*t] = h;
    }
  }
  __syncwarp();

  // ================= GAT2 linear (64->3 xl2, xr2) =================
  if (t < 24) {
#pragma unroll
    for (int u = 0; u < 2; u++) {
      float* sc = u ? sc1 : sc0;
      float a1 = ws[G2BL4 + l3], a2 = ws[G2BR4 + l3];
      const float* h1p = sc + SXR + n3*68;
#pragma unroll
      for (int c = 0; c < 64; c += 4) {
        float4 hh = *(const float4*)&h1p[c];
        float4 wl = *(const float4*)&ws[G2WLT + l3*64 + c];
        float4 wr = *(const float4*)&ws[G2WRT + l3*64 + c];
        a1 = fmaf(hh.x, wl.x, fmaf(hh.y, wl.y, fmaf(hh.z, wl.z, fmaf(hh.w, wl.w, a1))));
        a2 = fmaf(hh.x, wr.x, fmaf(hh.y, wr.y, fmaf(hh.z, wr.z, fmaf(hh.w, wr.w, a2))));
      }
      sc[SXL2 + n3*4 + l3] = a1;
      sc[SXR2 + n3*4 + l3] = a2;
    }
  }
  __syncwarp();

  // ================= GAT2 edge scores + softmax =================
#pragma unroll
  for (int u = 0; u < 2; u++) {
    float* sc = u ? sc1 : sc0;
    const int i = t >> 2;
    const int jj = (t & 3) * 2;
    float4 r   = *(const float4*)&sc[SXR2 + i*4];
    float4 l0  = *(const float4*)&sc[SXL2 + jj*4];
    float4 l1  = *(const float4*)&sc[SXL2 + (jj+1)*4];
    float4 we  = *(const float4*)&ws[G2WE4];
    float4 at  = *(const float4*)&ws[G2ATT4];
    float2 em = *(const float2*)&sc[SEM + 2*t];
    float mk0 = (em.x >= 0.f) ? 1.f : 0.f;
    float mk1 = (em.y >= 0.f) ? 1.f : 0.f;
    float acc0 = 0.f, acc1 = 0.f;
    acc0 = fmaf(lrelu(fmaf(em.x, we.x, r.x) + l0.x), at.x, acc0);
    acc1 = fmaf(lrelu(fmaf(em.y, we.x, r.x) + l1.x), at.x, acc1);
    acc0 = fmaf(lrelu(fmaf(em.x, we.y, r.y) + l0.y), at.y, acc0);
    acc1 = fmaf(lrelu(fmaf(em.y, we.y, r.y) + l1.y), at.y, acc1);
    acc0 = fmaf(lrelu(fmaf(em.x, we.z, r.z) + l0.z), at.z, acc0);
    acc1 = fmaf(lrelu(fmaf(em.y, we.z, r.z) + l1.z), at.z, acc1);
    float e0 = (mk0 != 0.f) ? acc0 : -1e30f;
    float e1 = (mk1 != 0.f) ? acc1 : -1e30f;
    float m = fmaxf(e0, e1);
    m = fmaxf(m, __shfl_xor_sync(0xffffffffu, m, 1));
    m = fmaxf(m, __shfl_xor_sync(0xffffffffu, m, 2));
    float x0 = __expf(e0 - m), x1 = __expf(e1 - m);
    float sden = x0 + x1;
    sden += __shfl_xor_sync(0xffffffffu, sden, 1);
    sden += __shfl_xor_sync(0xffffffffu, sden, 2);
    float inv = frcp(sden);
    *(float2*)&sc[SALPHA + 2*t] = make_float2(x0*inv*mk0, x1*inv*mk1);
  }
  __syncwarp();

  // ================= GAT2 aggregation + skip -> combined =================
  if (t < 24) {
#pragma unroll
    for (int u = 0; u < 2; u++) {
      float* sc = u ? sc1 : sc0;
      float acc = ws[G2BIAS4 + l3];
#pragma unroll
      for (int j = 0; j < 8; j++)
        acc = fmaf(sc[SALPHA + n3*8 + j], sc[SXL2 + j*4 + l3], acc);
      float4 la = *(const float4*)&sc[SLAT + n3*4];
      acc += fmaf(la.x, ws[SKW + l3],
             fmaf(la.y, ws[SKW + 3 + l3],
             fmaf(la.z, ws[SKW + 6 + l3], ws[SKB + l3])));
      sc[SCOMB + n3*4 + l3] = acc;
    }
  }
  __syncwarp();

  // ================= decoder L1 (3->64) =================
  {
    float w0a=ws[DW1+t],    w1a=ws[DW1+64+t],    w2a=ws[DW1+128+t],    ba=ws[DB1+t];
    float w0b=ws[DW1+t+32], w1b=ws[DW1+64+t+32], w2b=ws[DW1+128+t+32], bb=ws[DB1+t+32];
#pragma unroll
    for (int u = 0; u < 2; u++) {
      float* sc = u ? sc1 : sc0;
      float va[8], vb[8];
#pragma unroll
      for (int n = 0; n < 8; n++) {
        float4 cm = *(const float4*)&sc[SCOMB + n*4];
        va[n] = fmaxf(fmaf(cm.x, w0a, fmaf(cm.y, w1a, fmaf(cm.z, w2a, ba))), 0.f);
        vb[n] = fmaxf(fmaf(cm.x, w0b, fmaf(cm.y, w1b, fmaf(cm.z, w2b, bb))), 0.f);
      }
      *(float4*)&sc[SA + t*8]          = make_float4(va[0],va[1],va[2],va[3]);
      *(float4*)&sc[SA + t*8 + 4]      = make_float4(va[4],va[5],va[6],va[7]);
      *(float4*)&sc[SA + (t+32)*8]     = make_float4(vb[0],vb[1],vb[2],vb[3]);
      *(float4*)&sc[SA + (t+32)*8 + 4] = make_float4(vb[4],vb[5],vb[6],vb[7]);
    }
  }
  __syncwarp();

  // ================= decoder L2+L3 (dual-sample) =================
  mlp64_dual(sc0 + SA, sc1 + SA, sc0, sc1, ws + DW2P, ws + DB2P, ws + DW3P, t);

#pragma unroll
  for (int u = 0; u < 2; u++) {
    float* sc = u ? sc1 : sc0;
    const bool vU = u ? v1 : v0;
    const int sU = u ? s1 : s0;
    if (vU && t < 24)
      out[Btot*24 + sU*24 + t] = sc[SLATP + t] + ws[DB3 + l3];
  }
  __syncwarp();

  }  // chunk loop
}

extern "C" void kernel_launch(void* const* d_in, const int* in_sizes, int n_in,
                              void* d_out, int out_size)
{
  (void)n_in; (void)out_size;
  KParams kp;
  kp.x = (const float*)d_in[0];
  for (int i = 0; i < 28; i++) kp.w[i] = (const float*)d_in[i + 1];
  kp.B = in_sizes[0] / 8;
  kp.nChunks = (kp.B + SPB - 1) / SPB;

  cudaFuncSetAttribute(gae15_kernel, cudaFuncAttributeMaxDynamicSharedMemorySize, SMEM_BYTES);
  int grid = (kp.nChunks < GRID) ? kp.nChunks : GRID;
  gae15_kernel<<<grid, THREADS, SMEM_BYTES>>>(kp, (float*)d_out);
}

// round 17
// speedup vs baseline: 1.0297x; 1.0297x over previous
#include <cuda_runtime.h>

#define SPB 37           // samples per chunk: 18 warps x 2 + warp18 x 1
#define WARPS 19
#define THREADS (WARPS*32)   // 608
#define GRID 148             // persistent: one block per SM, warps loop over chunks

// ---- weight offsets in shared (floats) ----
enum {
  EW1=0, EB1=192, EW2P=256, EB2P=4352, EW3P=4416, EB3=4672,
  G1WL=4676, G1BL=4868, G1WR=4932, G1BR=5124, G1WE=5188, G1ATT=5252, G1BIAS=5316,
  G2WLT=5380, G2BL4=5572, G2WRT=5576, G2BR4=5768,
  G2WE4=5772, G2ATT4=5776, G2BIAS4=5780,
  SKW=5784, SKB=5796,
  DW1=5800, DB1=5992, DW2P=6056, DB2P=10152, DW3P=10216, DB3=10472,
  WTOT=10476
};
// ---- per-sample scratch (floats); heavy lifetime overlays ----
enum {
  SA=0, SLATP=512, SXL=0, SXR=544, SXL2=0, SXR2=32,
  SEM=1084, SX=1084, SALPHA=1148, SLAT=1212, SVIS=1244, SCOMB=1244,
  SPER=1276
};

#define SMEM_FLOATS (WTOT + SPB*SPER)
#define SMEM_BYTES  (SMEM_FLOATS*4)   // 230,752 B -> 1 block/SM

struct KParams {
  const float* x;
  const float* w[28];
  int B;
  int nChunks;
};

extern __shared__ float smem[];

__device__ __forceinline__ void cpy(float* dst, const float* src, int n, int tid) {
  for (int i = tid; i < n; i += THREADS) dst[i] = src[i];
}

__device__ __forceinline__ float lrelu(float h) { return fmaxf(h, 0.2f*h); }

__device__ __forceinline__ float frcp(float x) {
  float r; asm("rcp.approx.f32 %0, %1;" : "=f"(r) : "f"(x)); return r;
}
__device__ __forceinline__ float fsqrt_ap(float x) {
  float r; asm("sqrt.approx.f32 %0, %1;" : "=f"(r) : "f"(x)); return r;
}

__device__ __forceinline__ unsigned sm_u32(const void* p) {
  unsigned a;
  asm("{ .reg .u64 t; cvta.to.shared.u64 t, %1; cvt.u32.u64 %0, t; }"
      : "=r"(a) : "l"(p));
  return a;
}

// Dual-sample 8x64 @ 64x64 + relu + fused (64->3) projection; f32x2 with
// NODE-PAIR packed accumulators. Warp18 (sc1==sc0) duplicates; idempotent.
__device__ __forceinline__ void mlp64_dual(
    const float* __restrict__ in0, const float* __restrict__ in1,
    float* sc0, float* sc1,
    const float* __restrict__ Wp, const float* __restrict__ bp,
    const float* __restrict__ W3p, int t)
{
  const int u = t & 1, cg = t >> 1;
  const unsigned abase = sm_u32(u ? in1 : in0);
  const unsigned wbase = sm_u32(Wp) + cg*16u;

  float4 b4 = *(const float4*)&bp[cg*4];
  unsigned long long D0[4], D1[4], D2[4], D3[4];
  {
    unsigned long long bd0, bd1, bd2, bd3;
    asm("mov.b64 %0, {%1,%1};" : "=l"(bd0) : "f"(b4.x));
    asm("mov.b64 %0, {%1,%1};" : "=l"(bd1) : "f"(b4.y));
    asm("mov.b64 %0, {%1,%1};" : "=l"(bd2) : "f"(b4.z));
    asm("mov.b64 %0, {%1,%1};" : "=l"(bd3) : "f"(b4.w));
#pragma unroll
    for (int p = 0; p < 4; p++) { D0[p]=bd0; D1[p]=bd1; D2[p]=bd2; D3[p]=bd3; }
  }

#pragma unroll 8
  for (int k = 0; k < 64; k++) {
    unsigned aa = abase + (unsigned)(k*32);
    unsigned wa = wbase + (unsigned)(k*256);
    unsigned long long ar0, ar1, ar2, ar3, w01, w23;
    asm("ld.shared.v2.u64 {%0,%1}, [%2];" : "=l"(ar0), "=l"(ar1) : "r"(aa));
    asm("ld.shared.v2.u64 {%0,%1}, [%2];" : "=l"(ar2), "=l"(ar3) : "r"(aa+16u));
    asm("ld.shared.v2.u64 {%0,%1}, [%2];" : "=l"(w01), "=l"(w23) : "r"(wa));
    float w0, w1, w2, w3;
    asm("mov.b64 {%0,%1}, %2;" : "=f"(w0), "=f"(w1) : "l"(w01));
    asm("mov.b64 {%0,%1}, %2;" : "=f"(w2), "=f"(w3) : "l"(w23));
    unsigned long long wd0, wd1, wd2, wd3;
    asm("mov.b64 %0, {%1,%1};" : "=l"(wd0) : "f"(w0));
    asm("mov.b64 %0, {%1,%1};" : "=l"(wd1) : "f"(w1));
    asm("mov.b64 %0, {%1,%1};" : "=l"(wd2) : "f"(w2));
    asm("mov.b64 %0, {%1,%1};" : "=l"(wd3) : "f"(w3));
    asm("fma.rn.f32x2 %0, %1, %2, %0;" : "+l"(D0[0]) : "l"(wd0), "l"(ar0));
    asm("fma.rn.f32x2 %0, %1, %2, %0;" : "+l"(D0[1]) : "l"(wd0), "l"(ar1));
    asm("fma.rn.f32x2 %0, %1, %2, %0;" : "+l"(D0[2]) : "l"(wd0), "l"(ar2));
    asm("fma.rn.f32x2 %0, %1, %2, %0;" : "+l"(D0[3]) : "l"(wd0), "l"(ar3));
    asm("fma.rn.f32x2 %0, %1, %2, %0;" : "+l"(D1[0]) : "l"(wd1), "l"(ar0));
    asm("fma.rn.f32x2 %0, %1, %2, %0;" : "+l"(D1[1]) : "l"(wd1), "l"(ar1));
    asm("fma.rn.f32x2 %0, %1, %2, %0;" : "+l"(D1[2]) : "l"(wd1), "l"(ar2));
    asm("fma.rn.f32x2 %0, %1, %2, %0;" : "+l"(D1[3]) : "l"(wd1), "l"(ar3));
    asm("fma.rn.f32x2 %0, %1, %2, %0;" : "+l"(D2[0]) : "l"(wd2), "l"(ar0));
    asm("fma.rn.f32x2 %0, %1, %2, %0;" : "+l"(D2[1]) : "l"(wd2), "l"(ar1));
    asm("fma.rn.f32x2 %0, %1, %2, %0;" : "+l"(D2[2]) : "l"(wd2), "l"(ar2));
    asm("fma.rn.f32x2 %0, %1, %2, %0;" : "+l"(D2[3]) : "l"(wd2), "l"(ar3));
    asm("fma.rn.f32x2 %0, %1, %2, %0;" : "+l"(D3[0]) : "l"(wd3), "l"(ar0));
    asm("fma.rn.f32x2 %0, %1, %2, %0;" : "+l"(D3[1]) : "l"(wd3), "l"(ar1));
    asm("fma.rn.f32x2 %0, %1, %2, %0;" : "+l"(D3[2]) : "l"(wd3), "l"(ar2));
    asm("fma.rn.f32x2 %0, %1, %2, %0;" : "+l"(D3[3]) : "l"(wd3), "l"(ar3));
  }

  float A0[8], A1[8], A2[8], A3[8];
#pragma unroll
  for (int p = 0; p < 4; p++) {
    asm("mov.b64 {%0,%1}, %2;" : "=f"(A0[2*p]), "=f"(A0[2*p+1]) : "l"(D0[p]));
    asm("mov.b64 {%0,%1}, %2;" : "=f"(A1[2*p]), "=f"(A1[2*p+1]) : "l"(D1[p]));
    asm("mov.b64 {%0,%1}, %2;" : "=f"(A2[2*p]), "=f"(A2[2*p+1]) : "l"(D2[p]));
    asm("mov.b64 {%0,%1}, %2;" : "=f"(A3[2*p]), "=f"(A3[2*p+1]) : "l"(D3[p]));
  }
#pragma unroll
  for (int n = 0; n < 8; n++) {
    A0[n] = fmaxf(A0[n], 0.f); A1[n] = fmaxf(A1[n], 0.f);
    A2[n] = fmaxf(A2[n], 0.f); A3[n] = fmaxf(A3[n], 0.f);
  }

  const int p0i = cg*4;
  float4 E0 = *(const float4*)&W3p[(p0i+0)*4];
  float4 E1 = *(const float4*)&W3p[(p0i+1)*4];
  float4 E2 = *(const float4*)&W3p[(p0i+2)*4];
  float4 E3 = *(const float4*)&W3p[(p0i+3)*4];

  float p0[8], p1[8], p2[8];
#pragma unroll
  for (int n = 0; n < 8; n++) {
    p0[n] = fmaf(A0[n],E0.x, fmaf(A1[n],E1.x, fmaf(A2[n],E2.x, A3[n]*E3.x)));
    p1[n] = fmaf(A0[n],E0.y, fmaf(A1[n],E1.y, fmaf(A2[n],E2.y, A3[n]*E3.y)));
    p2[n] = fmaf(A0[n],E0.z, fmaf(A1[n],E1.z, fmaf(A2[n],E2.z, A3[n]*E3.z)));
  }

#pragma unroll
  for (int m = 2; m <= 16; m <<= 1) {
#pragma unroll
    for (int n = 0; n < 8; n++) {
      p0[n] += __shfl_xor_sync(0xffffffffu, p0[n], m);
      p1[n] += __shfl_xor_sync(0xffffffffu, p1[n], m);
      p2[n] += __shfl_xor_sync(0xffffffffu, p2[n], m);
    }
  }
  if (cg == 0) {
    float* d = (u ? sc1 : sc0) + SLATP;
#pragma unroll
    for (int n = 0; n < 8; n++) {
      d[n*3 + 0] = p0[n]; d[n*3 + 1] = p1[n]; d[n*3 + 2] = p2[n];
    }
  }
  __syncwarp();
}

__global__ __launch_bounds__(THREADS, 1)
void gae17_kernel(KParams kp, float* __restrict__ out)
{
  float* ws = smem;
  const int tid = threadIdx.x;

  // ================= stage weights (ONCE per SM) =================
  cpy(ws+EW1, kp.w[0], 192, tid); cpy(ws+EB1, kp.w[1], 64, tid);
  cpy(ws+EW2P, kp.w[2], 4096, tid);
  cpy(ws+EB2P, kp.w[3], 64, tid);
  { const float* w4 = kp.w[4];
    for (int i = tid; i < 256; i += THREADS) {
      int c = i >> 2, l = i & 3;
      ws[EW3P + i] = (l < 3) ? w4[c*3 + l] : 0.f;
    } }
  if (tid < 4) ws[EB3+tid] = (tid < 3) ? kp.w[5][tid] : 0.f;
  cpy(ws+G1WL, kp.w[6], 192, tid);  cpy(ws+G1BL, kp.w[7], 64, tid);
  cpy(ws+G1WR, kp.w[8], 192, tid);  cpy(ws+G1BR, kp.w[9], 64, tid);
  cpy(ws+G1WE, kp.w[10], 64, tid);  cpy(ws+G1ATT, kp.w[11], 64, tid);
  cpy(ws+G1BIAS, kp.w[12], 64, tid);
  { const float* wl = kp.w[13]; const float* wr = kp.w[15];
    for (int i = tid; i < 192; i += THREADS) {
      int k = i / 3, l = i - k*3;
      ws[G2WLT + l*64 + k] = wl[i];
      ws[G2WRT + l*64 + k] = wr[i];
    } }
  if (tid < 4) {
    ws[G2BL4 + tid]   = (tid < 3) ? kp.w[14][tid] : 0.f;
    ws[G2BR4 + tid]   = (tid < 3) ? kp.w[16][tid] : 0.f;
    ws[G2WE4 + tid]   = (tid < 3) ? kp.w[17][tid] : 0.f;
    ws[G2ATT4 + tid]  = (tid < 3) ? kp.w[18][tid] : 0.f;
    ws[G2BIAS4 + tid] = (tid < 3) ? kp.w[19][tid] : 0.f;
  }
  if (tid < 12) ws[SKW+tid] = (tid < 9) ? kp.w[20][tid] : 0.f;
  if (tid < 4)  ws[SKB+tid] = (tid < 3) ? kp.w[21][tid] : 0.f;
  cpy(ws+DW1, kp.w[22], 192, tid); cpy(ws+DB1, kp.w[23], 64, tid);
  cpy(ws+DW2P, kp.w[24], 4096, tid);
  cpy(ws+DB2P, kp.w[25], 64, tid);
  { const float* w26 = kp.w[26];
    for (int i = tid; i < 256; i += THREADS) {
      int c = i >> 2, l = i & 3;
      ws[DW3P + i] = (l < 3) ? w26[c*3 + l] : 0.f;
    } }
  if (tid < 4) ws[DB3+tid] = (tid < 3) ? kp.w[27][tid] : 0.f;

  const int g = tid >> 5;
  const int t = tid & 31;
  const int Btot = kp.B;
  const bool ok1 = (g < WARPS-1);
  const int slot1 = ok1 ? (2*g + 1) : 2*g;     // warp18: sc1 aliases sc0
  float* sc0 = smem + WTOT + (2*g)*SPER;
  float* sc1 = smem + WTOT + slot1*SPER;
  const int n3 = t / 3, l3 = t - n3*3;

  __syncthreads();   // weights visible to all warps; warps independent hereafter

  // ================= persistent chunk loop (warp-local) =================
  for (int chunk = blockIdx.x; chunk < kp.nChunks; chunk += GRID) {

  const int s0 = chunk*SPB + 2*g;
  const int s1 = s0 + 1;
  const bool v0 = (s0 < Btot);
  const bool v1 = ok1 && (s1 < Btot);

  if (t < 8) {
    sc0[SX + t] = kp.x[(v0 ? s0 : Btot-1)*8 + t];
    if (ok1) sc1[SX + t] = kp.x[(v1 ? s1 : Btot-1)*8 + t];
  }
  __syncwarp();

  // ================= encoder L1 (3->64), layout [c][n] stride 8 =================
  {
    float wn1 = ws[EW1+64+t],    wx1 = ws[EW1+128+t],    bb1 = ws[EB1+t];
    float wn2 = ws[EW1+64+t+32], wx2 = ws[EW1+128+t+32], bb2 = ws[EB1+t+32];
#pragma unroll
    for (int u = 0; u < 2; u++) {
      float* sc = u ? sc1 : sc0;
      float va[8], vb[8];
#pragma unroll
      for (int n = 0; n < 8; n++) {
        float xn = sc[SX + n];
        va[n] = fmaxf(fmaf(xn, wx1, fmaf((float)n, wn1, bb1)), 0.f);
        vb[n] = fmaxf(fmaf(xn, wx2, fmaf((float)n, wn2, bb2)), 0.f);
      }
      *(float4*)&sc[SA + t*8]          = make_float4(va[0],va[1],va[2],va[3]);
      *(float4*)&sc[SA + t*8 + 4]      = make_float4(va[4],va[5],va[6],va[7]);
      *(float4*)&sc[SA + (t+32)*8]     = make_float4(vb[0],vb[1],vb[2],vb[3]);
      *(float4*)&sc[SA + (t+32)*8 + 4] = make_float4(vb[4],vb[5],vb[6],vb[7]);
    }
  }
  __syncwarp();

  // ================= encoder L2+L3 (dual-sample) =================
  mlp64_dual(sc0 + SA, sc1 + SA, sc0, sc1, ws + EW2P, ws + EB2P, ws + EW3P, t);

#pragma unroll
  for (int u = 0; u < 2; u++) {
    float* sc = u ? sc1 : sc0;
    if (t < 24) sc[SLAT + n3*4 + l3] = sc[SLATP + t] + ws[EB3 + l3];
  }
  __syncwarp();

  // ================= normalize -> vis + xp/vis outputs (IEEE: feeds adj) ======
#pragma unroll
  for (int u = 0; u < 2; u++) {
    float* sc = u ? sc1 : sc0;
    const bool vU = u ? v1 : v0;
    const int sU = u ? s1 : s0;
    int ln_l = t >> 3, ln_n = t & 7;
    float v = sc[SLAT + ln_n*4 + ((ln_l < 3) ? ln_l : 0)];
    float sm = v;
    sm += __shfl_xor_sync(0xffffffffu, sm, 1);
    sm += __shfl_xor_sync(0xffffffffu, sm, 2);
    sm += __shfl_xor_sync(0xffffffffu, sm, 4);
    float c = v - sm*0.125f;
    float vv = c*c;
    vv += __shfl_xor_sync(0xffffffffu, vv, 1);
    vv += __shfl_xor_sync(0xffffffffu, vv, 2);
    vv += __shfl_xor_sync(0xffffffffu, vv, 4);
    float inv = 1.f / (sqrtf(vv * (1.f/7.f)) + 1e-8f);
    float visv = c*inv;
    if (t < 24) {
      sc[SVIS + ln_n*4 + ln_l] = visv;
      if (vU) {
        out[2*Btot*24 + sU*24 + ln_n*3 + ln_l] = visv;
        float xpv = (l3 == 0) ? 0.f : ((l3 == 1) ? (float)n3 : sc[SX + n3]);
        out[sU*24 + t] = xpv;
      }
    }
  }
  __syncwarp();

  // ================= Gabriel graph (2 pairs per lane per sample) =================
#pragma unroll
  for (int u = 0; u < 2; u++) {
    float* sc = u ? sc1 : sc0;
    const bool vU = u ? v1 : v0;
    const int sU = u ? s1 : s0;
    float4 Pv[8];
#pragma unroll
    for (int n = 0; n < 8; n++) Pv[n] = *(const float4*)&sc[SVIS + n*4];
    int i0 = t >> 3, j0 = t & 7;
    int i1 = (t + 32) >> 3;
    float4 pi0 = Pv[i0], pj0 = Pv[j0], pi1 = Pv[i1];
    float a0, d0, a1, d1;
    {
      float mx=(pi0.x+pj0.x)*0.5f, my=(pi0.y+pj0.y)*0.5f, mz=(pi0.z+pj0.z)*0.5f;
      float rx=pi0.x-mx, ry=pi0.y-my, rz=pi0.z-mz;
      float r2 = rx*rx+ry*ry+rz*rz;
      bool viol = false;
#pragma unroll
      for (int k = 0; k < 8; k++) {
        float ex=Pv[k].x-mx, ey=Pv[k].y-my, ez=Pv[k].z-mz;
        float d2 = ex*ex+ey*ey+ez*ez;
        viol |= (k != i0) && (k != j0) && (d2 < r2);
      }
      a0 = (!viol && (i0 != j0)) ? 1.f : 0.f;
      float dx=pi0.x-pj0.x, dy=pi0.y-pj0.y, dz=pi0.z-pj0.z;
      d0 = fsqrt_ap(dx*dx+dy*dy+dz*dz + 1e-30f);
    }
    {
      float mx=(pi1.x+pj0.x)*0.5f, my=(pi1.y+pj0.y)*0.5f, mz=(pi1.z+pj0.z)*0.5f;
      float rx=pi1.x-mx, ry=pi1.y-my, rz=pi1.z-mz;
      float r2 = rx*rx+ry*ry+rz*rz;
      bool viol = false;
#pragma unroll
      for (int k = 0; k < 8; k++) {
        float ex=Pv[k].x-mx, ey=Pv[k].y-my, ez=Pv[k].z-mz;
        float d2 = ex*ex+ey*ey+ez*ez;
        viol |= (k != i1) && (k != j0) && (d2 < r2);
      }
      a1 = (!viol && (i1 != j0)) ? 1.f : 0.f;
      float dx=pi1.x-pj0.x, dy=pi1.y-pj0.y, dz=pi1.z-pj0.z;
      d1 = fsqrt_ap(dx*dx+dy*dy+dz*dz + 1e-30f);
    }
    float as = a0 + a1, ds = a0*d0 + a1*d1;
#pragma unroll
    for (int m = 16; m; m >>= 1) {
      as += __shfl_xor_sync(0xffffffffu, as, m);
      ds += __shfl_xor_sync(0xffffffffu, ds, m);
    }
    float ma = ds * frcp(fmaxf(as, 1.f));
    sc[SEM + t]      = (i0 == j0) ? ma : (a0 > 0.f ? d0 : -1.f);
    sc[SEM + t + 32] = (i1 == j0) ? ma : (a1 > 0.f ? d1 : -1.f);
    if (vU) {
      out[3*Btot*24 + sU*64 + t]      = a0;
      out[3*Btot*24 + sU*64 + t + 32] = a1;
    }
  }
  __syncwarp();

  // ========= GAT1 linear (3->64 xl, xr), channel-pair lanes, float2 stores =====
  {
    float2 wl0 = *(const float2*)&ws[G1WL + 2*t];
    float2 wl1 = *(const float2*)&ws[G1WL + 64 + 2*t];
    float2 wl2 = *(const float2*)&ws[G1WL + 128 + 2*t];
    float2 bl  = *(const float2*)&ws[G1BL + 2*t];
    float2 wr0 = *(const float2*)&ws[G1WR + 2*t];
    float2 wr1 = *(const float2*)&ws[G1WR + 64 + 2*t];
    float2 wr2 = *(const float2*)&ws[G1WR + 128 + 2*t];
    float2 br  = *(const float2*)&ws[G1BR + 2*t];
#pragma unroll
    for (int u = 0; u < 2; u++) {
      float* sc = u ? sc1 : sc0;
#pragma unroll
      for (int n = 0; n < 8; n++) {
        float4 la = *(const float4*)&sc[SLAT + n*4];
        float2 xl, xr;
        xl.x = fmaf(la.x, wl0.x, fmaf(la.y, wl1.x, fmaf(la.z, wl2.x, bl.x)));
        xl.y = fmaf(la.x, wl0.y, fmaf(la.y, wl1.y, fmaf(la.z, wl2.y, bl.y)));
        xr.x = fmaf(la.x, wr0.x, fmaf(la.y, wr1.x, fmaf(la.z, wr2.x, br.x)));
        xr.y = fmaf(la.x, wr0.y, fmaf(la.y, wr1.y, fmaf(la.z, wr2.y, br.y)));
        *(float2*)&sc[SXL + n*68 + 2*t] = xl;
        *(float2*)&sc[SXR + n*68 + 2*t] = xr;
      }
    }
  }
  __syncwarp();

  // ================= GAT1 edge scores + softmax (pairs 2t, 2t+1) =================
#pragma unroll
  for (int u = 0; u < 2; u++) {
    float* sc = u ? sc1 : sc0;
    const int i = t >> 2;
    const int jj = (t & 3) * 2;
    const float* xr = sc + SXR + i*68;
    const float* xa = sc + SXL + jj*68;
    float2 em = *(const float2*)&sc[SEM + 2*t];
    float mk0 = (em.x >= 0.f) ? 1.f : 0.f;
    float mk1 = (em.y >= 0.f) ? 1.f : 0.f;
    float acc0 = 0.f, acc1 = 0.f;
#pragma unroll 8
    for (int c = 0; c < 64; c += 4) {
      float4 r  = *(const float4*)&xr[c];
      float4 l0 = *(const float4*)&xa[c];
      float4 l1 = *(const float4*)&xa[c + 68];
      float4 we = *(const float4*)&ws[G1WE + c];
      float4 at = *(const float4*)&ws[G1ATT + c];
      acc0 = fmaf(lrelu(fmaf(em.x, we.x, r.x) + l0.x), at.x, acc0);
      acc1 = fmaf(lrelu(fmaf(em.y, we.x, r.x) + l1.x), at.x, acc1);
      acc0 = fmaf(lrelu(fmaf(em.x, we.y, r.y) + l0.y), at.y, acc0);
      acc1 = fmaf(lrelu(fmaf(em.y, we.y, r.y) + l1.y), at.y, acc1);
      acc0 = fmaf(lrelu(fmaf(em.x, we.z, r.z) + l0.z), at.z, acc0);
      acc1 = fmaf(lrelu(fmaf(em.y, we.z, r.z) + l1.z), at.z, acc1);
      acc0 = fmaf(lrelu(fmaf(em.x, we.w, r.w) + l0.w), at.w, acc0);
      acc1 = fmaf(lrelu(fmaf(em.y, we.w, r.w) + l1.w), at.w, acc1);
    }
    float e0 = (mk0 != 0.f) ? acc0 : -1e30f;
    float e1 = (mk1 != 0.f) ? acc1 : -1e30f;
    float m = fmaxf(e0, e1);
    m = fmaxf(m, __shfl_xor_sync(0xffffffffu, m, 1));
    m = fmaxf(m, __shfl_xor_sync(0xffffffffu, m, 2));
    float x0 = __expf(e0 - m), x1 = __expf(e1 - m);
    float sden = x0 + x1;
    sden += __shfl_xor_sync(0xffffffffu, sden, 1);
    sden += __shfl_xor_sync(0xffffffffu, sden, 2);
    float inv = frcp(sden);
    *(float2*)&sc[SALPHA + 2*t] = make_float2(x0*inv*mk0, x1*inv*mk1);
  }
  __syncwarp();

  // ======== GAT1 aggregation -> h1 (into SXR), channel-pair float2 =============
#pragma unroll
  for (int u = 0; u < 2; u++) {
    float* sc = u ? sc1 : sc0;
    float2 acc[8];
    float2 b2 = *(const float2*)&ws[G1BIAS + 2*t];
#pragma unroll
    for (int i = 0; i < 8; i++) acc[i] = b2;
#pragma unroll
    for (int j = 0; j < 8; j += 2) {
      float2 xa = *(const float2*)&sc[SXL + j*68 + 2*t];
      float2 xb = *(const float2*)&sc[SXL + (j+1)*68 + 2*t];
#pragma unroll
      for (int i = 0; i < 8; i++) {
        float2 al = *(const float2*)&sc[SALPHA + i*8 + j];
        acc[i].x = fmaf(al.x, xa.x, fmaf(al.y, xb.x, acc[i].x));
        acc[i].y = fmaf(al.x, xa.y, fmaf(al.y, xb.y, acc[i].y));
      }
    }
    __syncwarp();
#pragma unroll
    for (int i = 0; i < 8; i++) {
      float2 h;
      h.x = fmaxf(acc[i].x, 0.f);
      h.y = fmaxf(acc[i].y, 0.f);
      *(float2*)&sc[SXR + i*68 + 2*t] = h;
    }
  }
  __syncwarp();

  // ================= GAT2 linear (64->3 xl2, xr2) =================
  if (t < 24) {
#pragma unroll
    for (int u = 0; u < 2; u++) {
      float* sc = u ? sc1 : sc0;
      float a1 = ws[G2BL4 + l3], a2 = ws[G2BR4 + l3];
      const float* h1p = sc + SXR + n3*68;
#pragma unroll
      for (int c = 0; c < 64; c += 4) {
        float4 hh = *(const float4*)&h1p[c];
        float4 wl = *(const float4*)&ws[G2WLT + l3*64 + c];
        float4 wr = *(const float4*)&ws[G2WRT + l3*64 + c];
        a1 = fmaf(hh.x, wl.x, fmaf(hh.y, wl.y, fmaf(hh.z, wl.z, fmaf(hh.w, wl.w, a1))));
        a2 = fmaf(hh.x, wr.x, fmaf(hh.y, wr.y, fmaf(hh.z, wr.z, fmaf(hh.w, wr.w, a2))));
      }
      sc[SXL2 + n3*4 + l3] = a1;
      sc[SXR2 + n3*4 + l3] = a2;
    }
  }
  __syncwarp();

  // ================= GAT2 edge scores + softmax =================
#pragma unroll
  for (int u = 0; u < 2; u++) {
    float* sc = u ? sc1 : sc0;
    const int i = t >> 2;
    const int jj = (t & 3) * 2;
    float4 r   = *(const float4*)&sc[SXR2 + i*4];
    float4 l0  = *(const float4*)&sc[SXL2 + jj*4];
    float4 l1  = *(const float4*)&sc[SXL2 + (jj+1)*4];
    float4 we  = *(const float4*)&ws[G2WE4];
    float4 at  = *(const float4*)&ws[G2ATT4];
    float2 em = *(const float2*)&sc[SEM + 2*t];
    float mk0 = (em.x >= 0.f) ? 1.f : 0.f;
    float mk1 = (em.y >= 0.f) ? 1.f : 0.f;
    float acc0 = 0.f, acc1 = 0.f;
    acc0 = fmaf(lrelu(fmaf(em.x, we.x, r.x) + l0.x), at.x, acc0);
    acc1 = fmaf(lrelu(fmaf(em.y, we.x, r.x) + l1.x), at.x, acc1);
    acc0 = fmaf(lrelu(fmaf(em.x, we.y, r.y) + l0.y), at.y, acc0);
    acc1 = fmaf(lrelu(fmaf(em.y, we.y, r.y) + l1.y), at.y, acc1);
    acc0 = fmaf(lrelu(fmaf(em.x, we.z, r.z) + l0.z), at.z, acc0);
    acc1 = fmaf(lrelu(fmaf(em.y, we.z, r.z) + l1.z), at.z, acc1);
    float e0 = (mk0 != 0.f) ? acc0 : -1e30f;
    float e1 = (mk1 != 0.f) ? acc1 : -1e30f;
    float m = fmaxf(e0, e1);
    m = fmaxf(m, __shfl_xor_sync(0xffffffffu, m, 1));
    m = fmaxf(m, __shfl_xor_sync(0xffffffffu, m, 2));
    float x0 = __expf(e0 - m), x1 = __expf(e1 - m);
    float sden = x0 + x1;
    sden += __shfl_xor_sync(0xffffffffu, sden, 1);
    sden += __shfl_xor_sync(0xffffffffu, sden, 2);
    float inv = frcp(sden);
    *(float2*)&sc[SALPHA + 2*t] = make_float2(x0*inv*mk0, x1*inv*mk1);
  }
  __syncwarp();

  // ================= GAT2 aggregation + skip -> combined =================
  if (t < 24) {
#pragma unroll
    for (int u = 0; u < 2; u++) {
      float* sc = u ? sc1 : sc0;
      float acc = ws[G2BIAS4 + l3];
#pragma unroll
      for (int j = 0; j < 8; j++)
        acc = fmaf(sc[SALPHA + n3*8 + j], sc[SXL2 + j*4 + l3], acc);
      float4 la = *(const float4*)&sc[SLAT + n3*4];
      acc += fmaf(la.x, ws[SKW + l3],
             fmaf(la.y, ws[SKW + 3 + l3],
             fmaf(la.z, ws[SKW + 6 + l3], ws[SKB + l3])));
      sc[SCOMB + n3*4 + l3] = acc;
    }
  }
  __syncwarp();

  // ================= decoder L1 (3->64) =================
  {
    float w0a=ws[DW1+t],    w1a=ws[DW1+64+t],    w2a=ws[DW1+128+t],    ba=ws[DB1+t];
    float w0b=ws[DW1+t+32], w1b=ws[DW1+64+t+32], w2b=ws[DW1+128+t+32], bb=ws[DB1+t+32];
#pragma unroll
    for (int u = 0; u < 2; u++) {
      float* sc = u ? sc1 : sc0;
      float va[8], vb[8];
#pragma unroll
      for (int n = 0; n < 8; n++) {
        float4 cm = *(const float4*)&sc[SCOMB + n*4];
        va[n] = fmaxf(fmaf(cm.x, w0a, fmaf(cm.y, w1a, fmaf(cm.z, w2a, ba))), 0.f);
        vb[n] = fmaxf(fmaf(cm.x, w0b, fmaf(cm.y, w1b, fmaf(cm.z, w2b, bb))), 0.f);
      }
      *(float4*)&sc[SA + t*8]          = make_float4(va[0],va[1],va[2],va[3]);
      *(float4*)&sc[SA + t*8 + 4]      = make_float4(va[4],va[5],va[6],va[7]);
      *(float4*)&sc[SA + (t+32)*8]     = make_float4(vb[0],vb[1],vb[2],vb[3]);
      *(float4*)&sc[SA + (t+32)*8 + 4] = make_float4(vb[4],vb[5],vb[6],vb[7]);
    }
  }
  __syncwarp();

  // ================= decoder L2+L3 (dual-sample) =================
  mlp64_dual(sc0 + SA, sc1 + SA, sc0, sc1, ws + DW2P, ws + DB2P, ws + DW3P, t);

#pragma unroll
  for (int u = 0; u < 2; u++) {
    float* sc = u ? sc1 : sc0;
    const bool vU = u ? v1 : v0;
    const int sU = u ? s1 : s0;
    if (vU && t < 24)
      out[Btot*24 + sU*24 + t] = sc[SLATP + t] + ws[DB3 + l3];
  }
  __syncwarp();

  }  // chunk loop
}

extern "C" void kernel_launch(void* const* d_in, const int* in_sizes, int n_in,
                              void* d_out, int out_size)
{
  (void)n_in; (void)out_size;
  KParams kp;
  kp.x = (const float*)d_in[0];
  for (int i = 0; i < 28; i++) kp.w[i] = (const float*)d_in[i + 1];
  kp.B = in_sizes[0] / 8;
  kp.nChunks = (kp.B + SPB - 1) / SPB;

  cudaFuncSetAttribute(gae17_kernel, cudaFuncAttributeMaxDynamicSharedMemorySize, SMEM_BYTES);
  int grid = (kp.nChunks < GRID) ? kp.nChunks : GRID;
  gae17_kernel<<<grid, THREADS, SMEM_BYTES>>>(kp, (float*)d_out);
}